// round 11
// baseline (speedup 1.0000x reference)
#include <cuda_runtime.h>
#include <cuda_bf16.h>
#include <cuda_fp16.h>
#include <cstdint>

#define NN 50000
#define DD 128
#define HHEADS 4
#define CCH 32
#define EE 600000
#define SCAN_BLKS 196  // 196*256 = 50176 >= NN

// Scratch (device globals: no allocation allowed)
__device__ __align__(256) float g_xt[(size_t)NN * DD];
__device__ __align__(256) __half g_hh[(size_t)NN * DD];  // fp16 h
__device__ __align__(256) float g_asrc[NN * HHEADS];
__device__ __align__(256) float g_adst[NN * HHEADS];
__device__ __align__(256) int g_cnt[NN];
__device__ __align__(256) int g_rowstart[NN + 1];
__device__ __align__(256) int g_cursor[NN];
__device__ __align__(256) int g_srcs[EE];
__device__ __align__(256) int g_blocksum[SCAN_BLKS];
// B = W^T as bf16 hi/lo, plain row-major [n][k]
__device__ __align__(256) __nv_bfloat16 g_Bhi[128 * 128];
__device__ __align__(256) __nv_bfloat16 g_Blo[128 * 128];

// ---------------------------------------------------------------------------
// helpers
// ---------------------------------------------------------------------------
__device__ __forceinline__ uint32_t smem_u32(const void* p) {
    uint32_t a;
    asm("{ .reg .u64 t; cvta.to.shared.u64 t, %1; cvt.u32.u64 %0, t; }" : "=r"(a) : "l"(p));
    return a;
}
__device__ __forceinline__ void ldmx4(uint32_t* r, uint32_t addr) {
    asm volatile("ldmatrix.sync.aligned.m8n8.x4.shared.b16 {%0,%1,%2,%3}, [%4];"
                 : "=r"(r[0]), "=r"(r[1]), "=r"(r[2]), "=r"(r[3]) : "r"(addr));
}
__device__ __forceinline__ void ldmx2(uint32_t* r, uint32_t addr) {
    asm volatile("ldmatrix.sync.aligned.m8n8.x2.shared.b16 {%0,%1}, [%2];"
                 : "=r"(r[0]), "=r"(r[1]) : "r"(addr));
}
__device__ __forceinline__ void mma16816(float* d, const uint32_t* a, const uint32_t* b) {
    asm volatile(
        "mma.sync.aligned.m16n8k16.row.col.f32.bf16.bf16.f32 "
        "{%0,%1,%2,%3}, {%4,%5,%6,%7}, {%8,%9}, {%0,%1,%2,%3};"
        : "+f"(d[0]), "+f"(d[1]), "+f"(d[2]), "+f"(d[3])
        : "r"(a[0]), "r"(a[1]), "r"(a[2]), "r"(a[3]), "r"(b[0]), "r"(b[1]));
}

#define SSTRIDE 136  // bf16 elements per smem row (272B: ldmatrix conflict-free)

// ---------------------------------------------------------------------------
// K0: one-time W conversion: Bt[n][k] = W[k][n] -> hi/lo bf16
// ---------------------------------------------------------------------------
__global__ __launch_bounds__(256)
void k_wconv(const float* __restrict__ Wg) {
    const int idx = blockIdx.x * 256 + threadIdx.x;
    if (idx >= 128 * 128) return;
    const int k = idx >> 7;
    const int n = idx & 127;
    const float w = __ldg(Wg + idx);  // W[k][n]
    const __nv_bfloat16 hi = __float2bfloat16(w);
    const __nv_bfloat16 lo = __float2bfloat16(w - __bfloat162float(hi));
    g_Bhi[n * 128 + k] = hi;
    g_Blo[n * 128 + k] = lo;
}

// ---------------------------------------------------------------------------
// K1: fused LayerNorm1 + mma.sync bf16-split GEMM + att-score epilogue.
// 512 threads (16 warps). Tile 128x128, K=128.
// ---------------------------------------------------------------------------
extern __shared__ __nv_bfloat16 smem_bf[];

__global__ __launch_bounds__(512, 1)
void k_ln_gemm(const float* __restrict__ x, const float* __restrict__ g1,
               const float* __restrict__ b1, const float* __restrict__ att_s,
               const float* __restrict__ att_d) {
    __nv_bfloat16* Ahi = smem_bf;
    __nv_bfloat16* Alo = smem_bf + 128 * SSTRIDE;
    __nv_bfloat16* Bhi = smem_bf + 2 * 128 * SSTRIDE;
    __nv_bfloat16* Blo = smem_bf + 3 * 128 * SSTRIDE;

    const int t = threadIdx.x;
    const int lane = t & 31;
    const int wid = t >> 5;
    const int row0 = blockIdx.x * 128;

    // Copy B (hi/lo) into padded smem
    {
        const int row = t >> 2;
        const int col0 = (t & 3) * 32;
        const uint4* sh = (const uint4*)(g_Bhi + row * 128 + col0);
        const uint4* sl = (const uint4*)(g_Blo + row * 128 + col0);
        uint4* dh = (uint4*)(Bhi + row * SSTRIDE + col0);
        uint4* dl = (uint4*)(Blo + row * SSTRIDE + col0);
#pragma unroll
        for (int i = 0; i < 4; i++) { dh[i] = sh[i]; dl[i] = sl[i]; }
    }

    // LayerNorm + A hi/lo into padded smem: 16 warps x 8 rows each
    const float4 gv = __ldg(((const float4*)g1) + lane);
    const float4 bv = __ldg(((const float4*)b1) + lane);
#pragma unroll 1
    for (int i = 0; i < 8; i++) {
        const int r = wid + 16 * i;
        const int gr = row0 + r;
        float4 v = make_float4(0.f, 0.f, 0.f, 0.f);
        if (gr < NN) v = ((const float4*)(x + (size_t)gr * DD))[lane];
        float s = v.x + v.y + v.z + v.w;
        float q = v.x * v.x + v.y * v.y + v.z * v.z + v.w * v.w;
#pragma unroll
        for (int o = 16; o >= 1; o >>= 1) {
            s += __shfl_xor_sync(0xffffffffu, s, o);
            q += __shfl_xor_sync(0xffffffffu, q, o);
        }
        const float m = s * (1.f / 128.f);
        const float var = q * (1.f / 128.f) - m * m;
        const float rstd = rsqrtf(var + 1e-5f);
        float4 o4;
        o4.x = (v.x - m) * rstd * gv.x + bv.x;
        o4.y = (v.y - m) * rstd * gv.y + bv.y;
        o4.z = (v.z - m) * rstd * gv.z + bv.z;
        o4.w = (v.w - m) * rstd * gv.w + bv.w;
        if (gr < NN) ((float4*)(g_xt + (size_t)gr * DD))[lane] = o4;

        __nv_bfloat162 h01 = __floats2bfloat162_rn(o4.x, o4.y);
        __nv_bfloat162 h23 = __floats2bfloat162_rn(o4.z, o4.w);
        __nv_bfloat162 l01 = __floats2bfloat162_rn(o4.x - __bfloat162float(h01.x),
                                                   o4.y - __bfloat162float(h01.y));
        __nv_bfloat162 l23 = __floats2bfloat162_rn(o4.z - __bfloat162float(h23.x),
                                                   o4.w - __bfloat162float(h23.y));
        uint2 hp, lp;
        hp.x = *(const uint32_t*)&h01; hp.y = *(const uint32_t*)&h23;
        lp.x = *(const uint32_t*)&l01; lp.y = *(const uint32_t*)&l23;
        *(uint2*)(Ahi + r * SSTRIDE + 4 * lane) = hp;
        *(uint2*)(Alo + r * SSTRIDE + 4 * lane) = lp;
    }
    __syncthreads();

    // ---- MMA phase: warp -> 32m x 32n ----
    const int mrow = (wid & 3) * 32;
    const int noff = (wid >> 2) * 32;
    const uint32_t sAhi = smem_u32(Ahi);
    const uint32_t sAlo = smem_u32(Alo);
    const uint32_t sBhi = smem_u32(Bhi);
    const uint32_t sBlo = smem_u32(Blo);

    float acc[2][4][4];
#pragma unroll
    for (int mf = 0; mf < 2; mf++)
#pragma unroll
        for (int f = 0; f < 4; f++)
#pragma unroll
            for (int e = 0; e < 4; e++) acc[mf][f][e] = 0.f;

    const int am = lane & 15;
    const int aksel = (lane >> 4) << 3;
    const int bn = lane & 7;
    const int bksel = ((lane >> 3) & 1) << 3;

#pragma unroll 1
    for (int k0 = 0; k0 < 8; k0++) {
        const int ak = k0 * 16 + aksel;
        const int bk = k0 * 16 + bksel;
        uint32_t ah0[4], ah1[4], al0[4], al1[4];
        const uint32_t aoff0 = (uint32_t)(((mrow + am) * SSTRIDE + ak) * 2);
        const uint32_t aoff1 = aoff0 + 16 * SSTRIDE * 2;
        ldmx4(ah0, sAhi + aoff0);
        ldmx4(ah1, sAhi + aoff1);
        ldmx4(al0, sAlo + aoff0);
        ldmx4(al1, sAlo + aoff1);
#pragma unroll
        for (int f = 0; f < 4; f++) {
            const uint32_t boff = (uint32_t)(((noff + 8 * f + bn) * SSTRIDE + bk) * 2);
            uint32_t bh[2], bl[2];
            ldmx2(bh, sBhi + boff);
            ldmx2(bl, sBlo + boff);
            mma16816(acc[0][f], ah0, bh);
            mma16816(acc[1][f], ah1, bh);
            mma16816(acc[0][f], ah0, bl);
            mma16816(acc[1][f], ah1, bl);
            mma16816(acc[0][f], al0, bh);
            mma16816(acc[1][f], al1, bh);
        }
    }

    // ---- Epilogue ----
    const int head = wid >> 2;
    float ps_lo[2] = {0.f, 0.f}, ps_hi[2] = {0.f, 0.f};
    float pd_lo[2] = {0.f, 0.f}, pd_hi[2] = {0.f, 0.f};

#pragma unroll
    for (int f = 0; f < 4; f++) {
        const int c = noff + 8 * f + (lane & 3) * 2;
        const float as0 = __ldg(att_s + c), as1 = __ldg(att_s + c + 1);
        const float ad0 = __ldg(att_d + c), ad1 = __ldg(att_d + c + 1);
#pragma unroll
        for (int mf = 0; mf < 2; mf++) {
            const int r_lo = row0 + mrow + 16 * mf + (lane >> 2);
            const int r_hi = r_lo + 8;
            const float d0 = acc[mf][f][0], d1 = acc[mf][f][1];
            const float d2 = acc[mf][f][2], d3 = acc[mf][f][3];
            if (r_lo < NN) *(__half2*)(g_hh + (size_t)r_lo * DD + c) = __floats2half2_rn(d0, d1);
            if (r_hi < NN) *(__half2*)(g_hh + (size_t)r_hi * DD + c) = __floats2half2_rn(d2, d3);
            ps_lo[mf] += d0 * as0 + d1 * as1;
            ps_hi[mf] += d2 * as0 + d3 * as1;
            pd_lo[mf] += d0 * ad0 + d1 * ad1;
            pd_hi[mf] += d2 * ad0 + d3 * ad1;
        }
    }
#pragma unroll
    for (int mf = 0; mf < 2; mf++) {
#pragma unroll
        for (int o = 1; o <= 2; o <<= 1) {
            ps_lo[mf] += __shfl_xor_sync(0xffffffffu, ps_lo[mf], o);
            ps_hi[mf] += __shfl_xor_sync(0xffffffffu, ps_hi[mf], o);
            pd_lo[mf] += __shfl_xor_sync(0xffffffffu, pd_lo[mf], o);
            pd_hi[mf] += __shfl_xor_sync(0xffffffffu, pd_hi[mf], o);
        }
    }
    if ((lane & 3) == 0) {
#pragma unroll
        for (int mf = 0; mf < 2; mf++) {
            const int r_lo = row0 + mrow + 16 * mf + (lane >> 2);
            const int r_hi = r_lo + 8;
            if (r_lo < NN) {
                g_asrc[r_lo * HHEADS + head] = ps_lo[mf];
                g_adst[r_lo * HHEADS + head] = pd_lo[mf];
            }
            if (r_hi < NN) {
                g_asrc[r_hi * HHEADS + head] = ps_hi[mf];
                g_adst[r_hi * HHEADS + head] = pd_hi[mf];
            }
        }
    }
}

// ---------------------------------------------------------------------------
// K3: degree histogram over dst
// ---------------------------------------------------------------------------
__global__ __launch_bounds__(256)
void k_hist(const int* __restrict__ ei) {
    const int g = blockIdx.x * blockDim.x + threadIdx.x;
    if (g >= EE) return;
    atomicAdd(&g_cnt[__ldg(ei + EE + g)], 1);
}

// ---------------------------------------------------------------------------
// K4a: block-local exclusive scan of g_cnt
// ---------------------------------------------------------------------------
__global__ __launch_bounds__(256)
void k_scan_blk() {
    __shared__ int wsums[8];
    const int t = threadIdx.x;
    const int idx = blockIdx.x * 256 + t;
    const int lane = t & 31, w = t >> 5;
    const int c = (idx < NN) ? g_cnt[idx] : 0;
    int v = c;
#pragma unroll
    for (int o = 1; o < 32; o <<= 1) {
        const int u = __shfl_up_sync(0xffffffffu, v, o);
        if (lane >= o) v += u;
    }
    if (lane == 31) wsums[w] = v;
    __syncthreads();
    if (w == 0) {
        int x2 = (lane < 8) ? wsums[lane] : 0;
#pragma unroll
        for (int o = 1; o < 8; o <<= 1) {
            const int u = __shfl_up_sync(0xffffffffu, x2, o);
            if (lane >= o) x2 += u;
        }
        if (lane < 8) wsums[lane] = x2;
    }
    __syncthreads();
    const int excl = v - c + ((w > 0) ? wsums[w - 1] : 0);
    if (idx < NN) g_rowstart[idx] = excl;
    if (t == 255) g_blocksum[blockIdx.x] = excl + c;
}

// ---------------------------------------------------------------------------
// K4b: add block offsets
// ---------------------------------------------------------------------------
__global__ __launch_bounds__(256)
void k_scan_fix() {
    __shared__ int red[9];
    const int t = threadIdx.x;
    const int blk = blockIdx.x;
    const int lane = t & 31, w = t >> 5;
    int v = (t < blk) ? g_blocksum[t] : 0;
#pragma unroll
    for (int o = 16; o >= 1; o >>= 1) v += __shfl_xor_sync(0xffffffffu, v, o);
    if (lane == 0) red[w] = v;
    __syncthreads();
    if (t == 0) {
        int s = 0;
#pragma unroll
        for (int i = 0; i < 8; i++) s += red[i];
        red[8] = s;
    }
    __syncthreads();
    const int off = red[8];
    const int idx = blk * 256 + t;
    if (idx < NN) {
        const int r = g_rowstart[idx] + off;
        g_rowstart[idx] = r;
        g_cursor[idx] = r;
    }
    if (blk == SCAN_BLKS - 1 && t == 0) g_rowstart[NN] = off + g_blocksum[blk];
}

// ---------------------------------------------------------------------------
// K5: scatter src ids into dst-sorted CSR
// ---------------------------------------------------------------------------
__global__ __launch_bounds__(256)
void k_scatter(const int* __restrict__ ei) {
    const int g = blockIdx.x * blockDim.x + threadIdx.x;
    if (g >= EE) return;
    const int s = __ldg(ei + g);
    const int d = __ldg(ei + EE + g);
    const int pos = atomicAdd(&g_cursor[d], 1);
    g_srcs[pos] = s;
}

// ---------------------------------------------------------------------------
// K6: fused gather + normalize + residual + LN2.
// TWO nodes per warp (independent chains, interleaved) for 2x MLP.
// ---------------------------------------------------------------------------
__global__ __launch_bounds__(256)
void k_gather_out(const float* __restrict__ bias, const float* __restrict__ g2,
                  const float* __restrict__ b2, float* __restrict__ out) {
    const int g = blockIdx.x * blockDim.x + threadIdx.x;
    const int q = g >> 5;
    const int n0 = 2 * q;
    if (n0 >= NN) return;
    const int n1 = n0 + 1;
    const bool has1 = (n1 < NN);
    const int l = g & 31;
    const int head = l >> 3;

    const float ad0 = g_adst[n0 * HHEADS + head];
    const float ad1 = has1 ? g_adst[n1 * HHEADS + head] : 0.f;

    // self-loop edges
    float wsum0, wsum1 = 0.f;
    float4 acc0, acc1 = make_float4(0.f, 0.f, 0.f, 0.f);
    {
        float a = g_asrc[n0 * HHEADS + head] + ad0;
        a = (a > 0.f) ? a : 0.2f * a;
        const float w = __expf(a);
        wsum0 = w;
        const uint2 u = *(const uint2*)(g_hh + (size_t)n0 * DD + 4 * l);
        const float2 fa = __half22float2(*(const __half2*)&u.x);
        const float2 fb = __half22float2(*(const __half2*)&u.y);
        acc0 = make_float4(w * fa.x, w * fa.y, w * fb.x, w * fb.y);
    }
    if (has1) {
        float a = g_asrc[n1 * HHEADS + head] + ad1;
        a = (a > 0.f) ? a : 0.2f * a;
        const float w = __expf(a);
        wsum1 = w;
        const uint2 u = *(const uint2*)(g_hh + (size_t)n1 * DD + 4 * l);
        const float2 fa = __half22float2(*(const __half2*)&u.x);
        const float2 fb = __half22float2(*(const __half2*)&u.y);
        acc1 = make_float4(w * fa.x, w * fa.y, w * fb.x, w * fb.y);
    }

    int j0 = g_rowstart[n0];
    const int e0 = g_rowstart[n0 + 1];
    int j1 = has1 ? e0 : 0;               // rowstart[n1] == rowstart[n0+1]
    const int e1 = has1 ? g_rowstart[n1 + 1] : 0;

#pragma unroll 1
    while (j0 < e0 || j1 < e1) {
        int cnt0 = e0 - j0; cnt0 = (cnt0 < 0) ? 0 : ((cnt0 > 32) ? 32 : cnt0);
        int cnt1 = e1 - j1; cnt1 = (cnt1 < 0) ? 0 : ((cnt1 > 32) ? 32 : cnt1);
        const int sv0 = (l < cnt0) ? __ldg(g_srcs + j0 + l) : 0;
        const int sv1 = (l < cnt1) ? __ldg(g_srcs + j1 + l) : 0;
        const int mx = (cnt0 > cnt1) ? cnt0 : cnt1;
#pragma unroll 1
        for (int k = 0; k < mx; k++) {
            const int s0 = __shfl_sync(0xffffffffu, sv0, k);
            const int s1 = __shfl_sync(0xffffffffu, sv1, k);
            if (k < cnt0) {
                float as = g_asrc[s0 * HHEADS + head] + ad0;
                const uint2 u = *(const uint2*)(g_hh + (size_t)s0 * DD + 4 * l);
                as = (as > 0.f) ? as : 0.2f * as;
                const float ww = __expf(as);
                wsum0 += ww;
                const float2 fa = __half22float2(*(const __half2*)&u.x);
                const float2 fb = __half22float2(*(const __half2*)&u.y);
                acc0.x += ww * fa.x;
                acc0.y += ww * fa.y;
                acc0.z += ww * fb.x;
                acc0.w += ww * fb.y;
            }
            if (k < cnt1) {
                float as = g_asrc[s1 * HHEADS + head] + ad1;
                const uint2 u = *(const uint2*)(g_hh + (size_t)s1 * DD + 4 * l);
                as = (as > 0.f) ? as : 0.2f * as;
                const float ww = __expf(as);
                wsum1 += ww;
                const float2 fa = __half22float2(*(const __half2*)&u.x);
                const float2 fb = __half22float2(*(const __half2*)&u.y);
                acc1.x += ww * fa.x;
                acc1.y += ww * fa.y;
                acc1.z += ww * fb.x;
                acc1.w += ww * fb.y;
            }
        }
        j0 += 32; j1 += 32;
    }

    const float4 bv = __ldg(((const float4*)bias) + l);
    const float4 gv = __ldg(((const float4*)g2) + l);
    const float4 b2v = __ldg(((const float4*)b2) + l);

#pragma unroll
    for (int p = 0; p < 2; p++) {
        const int n = (p == 0) ? n0 : n1;
        if (p == 1 && !has1) break;
        const float wsum = (p == 0) ? wsum0 : wsum1;
        const float4 acc = (p == 0) ? acc0 : acc1;
        const float inv = 1.f / (wsum + 1e-16f);
        const float4 xv = ((const float4*)(g_xt + (size_t)n * DD))[l];
        float4 v;
        v.x = xv.x + acc.x * inv + bv.x;
        v.y = xv.y + acc.y * inv + bv.y;
        v.z = xv.z + acc.z * inv + bv.z;
        v.w = xv.w + acc.w * inv + bv.w;

        float ssum = v.x + v.y + v.z + v.w;
        float qq = v.x * v.x + v.y * v.y + v.z * v.z + v.w * v.w;
#pragma unroll
        for (int o = 16; o >= 1; o >>= 1) {
            ssum += __shfl_xor_sync(0xffffffffu, ssum, o);
            qq += __shfl_xor_sync(0xffffffffu, qq, o);
        }
        const float m = ssum * (1.f / 128.f);
        const float var = qq * (1.f / 128.f) - m * m;
        const float rstd = rsqrtf(var + 1e-5f);
        float4 o4;
        o4.x = (v.x - m) * rstd * gv.x + b2v.x;
        o4.y = (v.y - m) * rstd * gv.y + b2v.y;
        o4.z = (v.z - m) * rstd * gv.z + b2v.z;
        o4.w = (v.w - m) * rstd * gv.w + b2v.w;
        ((float4*)(out + (size_t)n * DD))[l] = o4;
    }
}

// ---------------------------------------------------------------------------
extern "C" void kernel_launch(void* const* d_in, const int* in_sizes, int n_in,
                              void* d_out, int out_size) {
    const float* x     = (const float*)d_in[0];
    const int*   ei    = (const int*)d_in[1];
    // d_in[2] edge_attr, d_in[3] timestamps: unused by reference
    const float* Wg    = (const float*)d_in[4];
    const float* att_s = (const float*)d_in[5];
    const float* att_d = (const float*)d_in[6];
    const float* bias  = (const float*)d_in[7];
    const float* g1    = (const float*)d_in[8];
    const float* b1    = (const float*)d_in[9];
    const float* g2    = (const float*)d_in[10];
    const float* b2    = (const float*)d_in[11];
    float* out = (float*)d_out;

    void* p_cnt = nullptr;
    cudaGetSymbolAddress(&p_cnt, g_cnt);
    cudaMemsetAsync(p_cnt, 0, (size_t)NN * sizeof(int), 0);

    const int smem_bytes = 4 * 128 * SSTRIDE * (int)sizeof(__nv_bfloat16);  // 139264
    cudaFuncSetAttribute(k_ln_gemm, cudaFuncAttributeMaxDynamicSharedMemorySize, smem_bytes);

    k_wconv<<<64, 256>>>(Wg);
    k_hist<<<(EE + 255) / 256, 256>>>(ei);
    k_ln_gemm<<<(NN + 127) / 128, 512, smem_bytes>>>(x, g1, b1, att_s, att_d);
    k_scan_blk<<<SCAN_BLKS, 256>>>();
    k_scan_fix<<<SCAN_BLKS, 256>>>();
    k_scatter<<<(EE + 255) / 256, 256>>>(ei);
    const int nwarp = (NN + 1) / 2;
    k_gather_out<<<(nwarp * 32 + 255) / 256, 256>>>(bias, g2, b2, out);
}

// round 12
// speedup vs baseline: 1.1828x; 1.1828x over previous
#include <cuda_runtime.h>
#include <cuda_bf16.h>
#include <cuda_fp16.h>
#include <cstdint>

#define NN 50000
#define DD 128
#define HHEADS 4
#define CCH 32
#define EE 600000
#define SCAN_BLKS 196  // 196*256 = 50176 >= NN

// Scratch (device globals: no allocation allowed)
__device__ __align__(256) float g_xt[(size_t)NN * DD];
__device__ __align__(256) __half g_hh[(size_t)NN * DD];  // fp16 h
__device__ __align__(256) float g_asrc[NN * HHEADS];
__device__ __align__(256) float g_adst[NN * HHEADS];
__device__ __align__(256) int g_cnt[NN];
__device__ __align__(256) int g_rowstart[NN + 1];
__device__ __align__(256) int g_cursor[NN];
__device__ __align__(256) int g_srcs[EE];
__device__ __align__(256) int g_blocksum[SCAN_BLKS];
// B = W^T as bf16 hi/lo, plain row-major [n][k]
__device__ __align__(256) __nv_bfloat16 g_Bhi[128 * 128];
__device__ __align__(256) __nv_bfloat16 g_Blo[128 * 128];

// Secondary stream + fork/join events, created ONCE at static init (before the
// harness's memory checkpoints; no device-memory allocation APIs involved).
namespace {
struct StreamHolder {
    cudaStream_t s2 = nullptr;
    cudaEvent_t ev_fork = nullptr, ev_join = nullptr;
    bool ok = false;
    StreamHolder() {
        ok = (cudaStreamCreateWithFlags(&s2, cudaStreamNonBlocking) == cudaSuccess) &&
             (cudaEventCreateWithFlags(&ev_fork, cudaEventDisableTiming) == cudaSuccess) &&
             (cudaEventCreateWithFlags(&ev_join, cudaEventDisableTiming) == cudaSuccess);
    }
};
StreamHolder g_sh;
}  // namespace

// ---------------------------------------------------------------------------
// helpers
// ---------------------------------------------------------------------------
__device__ __forceinline__ uint32_t smem_u32(const void* p) {
    uint32_t a;
    asm("{ .reg .u64 t; cvta.to.shared.u64 t, %1; cvt.u32.u64 %0, t; }" : "=r"(a) : "l"(p));
    return a;
}
__device__ __forceinline__ void ldmx4(uint32_t* r, uint32_t addr) {
    asm volatile("ldmatrix.sync.aligned.m8n8.x4.shared.b16 {%0,%1,%2,%3}, [%4];"
                 : "=r"(r[0]), "=r"(r[1]), "=r"(r[2]), "=r"(r[3]) : "r"(addr));
}
__device__ __forceinline__ void ldmx2(uint32_t* r, uint32_t addr) {
    asm volatile("ldmatrix.sync.aligned.m8n8.x2.shared.b16 {%0,%1}, [%2];"
                 : "=r"(r[0]), "=r"(r[1]) : "r"(addr));
}
__device__ __forceinline__ void mma16816(float* d, const uint32_t* a, const uint32_t* b) {
    asm volatile(
        "mma.sync.aligned.m16n8k16.row.col.f32.bf16.bf16.f32 "
        "{%0,%1,%2,%3}, {%4,%5,%6,%7}, {%8,%9}, {%0,%1,%2,%3};"
        : "+f"(d[0]), "+f"(d[1]), "+f"(d[2]), "+f"(d[3])
        : "r"(a[0]), "r"(a[1]), "r"(a[2]), "r"(a[3]), "r"(b[0]), "r"(b[1]));
}

#define SSTRIDE 136  // bf16 elements per smem row (272B: ldmatrix conflict-free)

// ---------------------------------------------------------------------------
// K0: one-time W conversion: Bt[n][k] = W[k][n] -> hi/lo bf16
// ---------------------------------------------------------------------------
__global__ __launch_bounds__(256)
void k_wconv(const float* __restrict__ Wg) {
    const int idx = blockIdx.x * 256 + threadIdx.x;
    if (idx >= 128 * 128) return;
    const int k = idx >> 7;
    const int n = idx & 127;
    const float w = __ldg(Wg + idx);  // W[k][n]
    const __nv_bfloat16 hi = __float2bfloat16(w);
    const __nv_bfloat16 lo = __float2bfloat16(w - __bfloat162float(hi));
    g_Bhi[n * 128 + k] = hi;
    g_Blo[n * 128 + k] = lo;
}

// ---------------------------------------------------------------------------
// K1: fused LayerNorm1 + mma.sync bf16-split GEMM + att-score epilogue.
// 512 threads (16 warps). Tile 128x128, K=128.
// ---------------------------------------------------------------------------
extern __shared__ __nv_bfloat16 smem_bf[];

__global__ __launch_bounds__(512, 1)
void k_ln_gemm(const float* __restrict__ x, const float* __restrict__ g1,
               const float* __restrict__ b1, const float* __restrict__ att_s,
               const float* __restrict__ att_d) {
    __nv_bfloat16* Ahi = smem_bf;
    __nv_bfloat16* Alo = smem_bf + 128 * SSTRIDE;
    __nv_bfloat16* Bhi = smem_bf + 2 * 128 * SSTRIDE;
    __nv_bfloat16* Blo = smem_bf + 3 * 128 * SSTRIDE;

    const int t = threadIdx.x;
    const int lane = t & 31;
    const int wid = t >> 5;
    const int row0 = blockIdx.x * 128;

    // Copy B (hi/lo) into padded smem
    {
        const int row = t >> 2;
        const int col0 = (t & 3) * 32;
        const uint4* sh = (const uint4*)(g_Bhi + row * 128 + col0);
        const uint4* sl = (const uint4*)(g_Blo + row * 128 + col0);
        uint4* dh = (uint4*)(Bhi + row * SSTRIDE + col0);
        uint4* dl = (uint4*)(Blo + row * SSTRIDE + col0);
#pragma unroll
        for (int i = 0; i < 4; i++) { dh[i] = sh[i]; dl[i] = sl[i]; }
    }

    // LayerNorm + A hi/lo into padded smem: 16 warps x 8 rows each
    const float4 gv = __ldg(((const float4*)g1) + lane);
    const float4 bv = __ldg(((const float4*)b1) + lane);
#pragma unroll 1
    for (int i = 0; i < 8; i++) {
        const int r = wid + 16 * i;
        const int gr = row0 + r;
        float4 v = make_float4(0.f, 0.f, 0.f, 0.f);
        if (gr < NN) v = ((const float4*)(x + (size_t)gr * DD))[lane];
        float s = v.x + v.y + v.z + v.w;
        float q = v.x * v.x + v.y * v.y + v.z * v.z + v.w * v.w;
#pragma unroll
        for (int o = 16; o >= 1; o >>= 1) {
            s += __shfl_xor_sync(0xffffffffu, s, o);
            q += __shfl_xor_sync(0xffffffffu, q, o);
        }
        const float m = s * (1.f / 128.f);
        const float var = q * (1.f / 128.f) - m * m;
        const float rstd = rsqrtf(var + 1e-5f);
        float4 o4;
        o4.x = (v.x - m) * rstd * gv.x + bv.x;
        o4.y = (v.y - m) * rstd * gv.y + bv.y;
        o4.z = (v.z - m) * rstd * gv.z + bv.z;
        o4.w = (v.w - m) * rstd * gv.w + bv.w;
        if (gr < NN) ((float4*)(g_xt + (size_t)gr * DD))[lane] = o4;

        __nv_bfloat162 h01 = __floats2bfloat162_rn(o4.x, o4.y);
        __nv_bfloat162 h23 = __floats2bfloat162_rn(o4.z, o4.w);
        __nv_bfloat162 l01 = __floats2bfloat162_rn(o4.x - __bfloat162float(h01.x),
                                                   o4.y - __bfloat162float(h01.y));
        __nv_bfloat162 l23 = __floats2bfloat162_rn(o4.z - __bfloat162float(h23.x),
                                                   o4.w - __bfloat162float(h23.y));
        uint2 hp, lp;
        hp.x = *(const uint32_t*)&h01; hp.y = *(const uint32_t*)&h23;
        lp.x = *(const uint32_t*)&l01; lp.y = *(const uint32_t*)&l23;
        *(uint2*)(Ahi + r * SSTRIDE + 4 * lane) = hp;
        *(uint2*)(Alo + r * SSTRIDE + 4 * lane) = lp;
    }
    __syncthreads();

    // ---- MMA phase: warp -> 32m x 32n ----
    const int mrow = (wid & 3) * 32;
    const int noff = (wid >> 2) * 32;
    const uint32_t sAhi = smem_u32(Ahi);
    const uint32_t sAlo = smem_u32(Alo);
    const uint32_t sBhi = smem_u32(Bhi);
    const uint32_t sBlo = smem_u32(Blo);

    float acc[2][4][4];
#pragma unroll
    for (int mf = 0; mf < 2; mf++)
#pragma unroll
        for (int f = 0; f < 4; f++)
#pragma unroll
            for (int e = 0; e < 4; e++) acc[mf][f][e] = 0.f;

    const int am = lane & 15;
    const int aksel = (lane >> 4) << 3;
    const int bn = lane & 7;
    const int bksel = ((lane >> 3) & 1) << 3;

#pragma unroll 1
    for (int k0 = 0; k0 < 8; k0++) {
        const int ak = k0 * 16 + aksel;
        const int bk = k0 * 16 + bksel;
        uint32_t ah0[4], ah1[4], al0[4], al1[4];
        const uint32_t aoff0 = (uint32_t)(((mrow + am) * SSTRIDE + ak) * 2);
        const uint32_t aoff1 = aoff0 + 16 * SSTRIDE * 2;
        ldmx4(ah0, sAhi + aoff0);
        ldmx4(ah1, sAhi + aoff1);
        ldmx4(al0, sAlo + aoff0);
        ldmx4(al1, sAlo + aoff1);
#pragma unroll
        for (int f = 0; f < 4; f++) {
            const uint32_t boff = (uint32_t)(((noff + 8 * f + bn) * SSTRIDE + bk) * 2);
            uint32_t bh[2], bl[2];
            ldmx2(bh, sBhi + boff);
            ldmx2(bl, sBlo + boff);
            mma16816(acc[0][f], ah0, bh);
            mma16816(acc[1][f], ah1, bh);
            mma16816(acc[0][f], ah0, bl);
            mma16816(acc[1][f], ah1, bl);
            mma16816(acc[0][f], al0, bh);
            mma16816(acc[1][f], al1, bh);
        }
    }

    // ---- Epilogue: store h (fp16) + fused attention scores ----
    const int head = wid >> 2;
    float ps_lo[2] = {0.f, 0.f}, ps_hi[2] = {0.f, 0.f};
    float pd_lo[2] = {0.f, 0.f}, pd_hi[2] = {0.f, 0.f};

#pragma unroll
    for (int f = 0; f < 4; f++) {
        const int c = noff + 8 * f + (lane & 3) * 2;
        const float as0 = __ldg(att_s + c), as1 = __ldg(att_s + c + 1);
        const float ad0 = __ldg(att_d + c), ad1 = __ldg(att_d + c + 1);
#pragma unroll
        for (int mf = 0; mf < 2; mf++) {
            const int r_lo = row0 + mrow + 16 * mf + (lane >> 2);
            const int r_hi = r_lo + 8;
            const float d0 = acc[mf][f][0], d1 = acc[mf][f][1];
            const float d2 = acc[mf][f][2], d3 = acc[mf][f][3];
            if (r_lo < NN) *(__half2*)(g_hh + (size_t)r_lo * DD + c) = __floats2half2_rn(d0, d1);
            if (r_hi < NN) *(__half2*)(g_hh + (size_t)r_hi * DD + c) = __floats2half2_rn(d2, d3);
            ps_lo[mf] += d0 * as0 + d1 * as1;
            ps_hi[mf] += d2 * as0 + d3 * as1;
            pd_lo[mf] += d0 * ad0 + d1 * ad1;
            pd_hi[mf] += d2 * ad0 + d3 * ad1;
        }
    }
#pragma unroll
    for (int mf = 0; mf < 2; mf++) {
#pragma unroll
        for (int o = 1; o <= 2; o <<= 1) {
            ps_lo[mf] += __shfl_xor_sync(0xffffffffu, ps_lo[mf], o);
            ps_hi[mf] += __shfl_xor_sync(0xffffffffu, ps_hi[mf], o);
            pd_lo[mf] += __shfl_xor_sync(0xffffffffu, pd_lo[mf], o);
            pd_hi[mf] += __shfl_xor_sync(0xffffffffu, pd_hi[mf], o);
        }
    }
    if ((lane & 3) == 0) {
#pragma unroll
        for (int mf = 0; mf < 2; mf++) {
            const int r_lo = row0 + mrow + 16 * mf + (lane >> 2);
            const int r_hi = r_lo + 8;
            if (r_lo < NN) {
                g_asrc[r_lo * HHEADS + head] = ps_lo[mf];
                g_adst[r_lo * HHEADS + head] = pd_lo[mf];
            }
            if (r_hi < NN) {
                g_asrc[r_hi * HHEADS + head] = ps_hi[mf];
                g_adst[r_hi * HHEADS + head] = pd_hi[mf];
            }
        }
    }
}

// ---------------------------------------------------------------------------
// K3: degree histogram over dst
// ---------------------------------------------------------------------------
__global__ __launch_bounds__(256)
void k_hist(const int* __restrict__ ei) {
    const int g = blockIdx.x * blockDim.x + threadIdx.x;
    if (g >= EE) return;
    atomicAdd(&g_cnt[__ldg(ei + EE + g)], 1);
}

// ---------------------------------------------------------------------------
// K4a: block-local exclusive scan of g_cnt
// ---------------------------------------------------------------------------
__global__ __launch_bounds__(256)
void k_scan_blk() {
    __shared__ int wsums[8];
    const int t = threadIdx.x;
    const int idx = blockIdx.x * 256 + t;
    const int lane = t & 31, w = t >> 5;
    const int c = (idx < NN) ? g_cnt[idx] : 0;
    int v = c;
#pragma unroll
    for (int o = 1; o < 32; o <<= 1) {
        const int u = __shfl_up_sync(0xffffffffu, v, o);
        if (lane >= o) v += u;
    }
    if (lane == 31) wsums[w] = v;
    __syncthreads();
    if (w == 0) {
        int x2 = (lane < 8) ? wsums[lane] : 0;
#pragma unroll
        for (int o = 1; o < 8; o <<= 1) {
            const int u = __shfl_up_sync(0xffffffffu, x2, o);
            if (lane >= o) x2 += u;
        }
        if (lane < 8) wsums[lane] = x2;
    }
    __syncthreads();
    const int excl = v - c + ((w > 0) ? wsums[w - 1] : 0);
    if (idx < NN) g_rowstart[idx] = excl;
    if (t == 255) g_blocksum[blockIdx.x] = excl + c;
}

// ---------------------------------------------------------------------------
// K4b: add block offsets
// ---------------------------------------------------------------------------
__global__ __launch_bounds__(256)
void k_scan_fix() {
    __shared__ int red[9];
    const int t = threadIdx.x;
    const int blk = blockIdx.x;
    const int lane = t & 31, w = t >> 5;
    int v = (t < blk) ? g_blocksum[t] : 0;
#pragma unroll
    for (int o = 16; o >= 1; o >>= 1) v += __shfl_xor_sync(0xffffffffu, v, o);
    if (lane == 0) red[w] = v;
    __syncthreads();
    if (t == 0) {
        int s = 0;
#pragma unroll
        for (int i = 0; i < 8; i++) s += red[i];
        red[8] = s;
    }
    __syncthreads();
    const int off = red[8];
    const int idx = blk * 256 + t;
    if (idx < NN) {
        const int r = g_rowstart[idx] + off;
        g_rowstart[idx] = r;
        g_cursor[idx] = r;
    }
    if (blk == SCAN_BLKS - 1 && t == 0) g_rowstart[NN] = off + g_blocksum[blk];
}

// ---------------------------------------------------------------------------
// K5: scatter src ids into dst-sorted CSR
// ---------------------------------------------------------------------------
__global__ __launch_bounds__(256)
void k_scatter(const int* __restrict__ ei) {
    const int g = blockIdx.x * blockDim.x + threadIdx.x;
    if (g >= EE) return;
    const int s = __ldg(ei + g);
    const int d = __ldg(ei + EE + g);
    const int pos = atomicAdd(&g_cursor[d], 1);
    g_srcs[pos] = s;
}

// ---------------------------------------------------------------------------
// K6: fused gather-aggregate + normalize + residual + LN2. One warp per node.
// (frozen: identical to the 101.2us version)
// ---------------------------------------------------------------------------
__global__ __launch_bounds__(256)
void k_gather_out(const float* __restrict__ bias, const float* __restrict__ g2,
                  const float* __restrict__ b2, float* __restrict__ out) {
    const int g = blockIdx.x * blockDim.x + threadIdx.x;
    const int n = g >> 5;
    if (n >= NN) return;
    const int l = g & 31;
    const int head = l >> 3;

    const float ad = g_adst[n * HHEADS + head];

    // self-loop edge
    float a = g_asrc[n * HHEADS + head] + ad;
    a = (a > 0.f) ? a : 0.2f * a;
    float w = __expf(a);
    float wsum = w;
    float4 acc;
    {
        const uint2 u = *(const uint2*)(g_hh + (size_t)n * DD + 4 * l);
        const float2 fa = __half22float2(*(const __half2*)&u.x);
        const float2 fb = __half22float2(*(const __half2*)&u.y);
        acc = make_float4(w * fa.x, w * fa.y, w * fb.x, w * fb.y);
    }

    const int rs = g_rowstart[n];
    const int re = g_rowstart[n + 1];
#pragma unroll 1
    for (int j = rs; j < re; j += 32) {
        const int cnt = min(32, re - j);
        const int sv = (l < cnt) ? __ldg(g_srcs + j + l) : 0;
#pragma unroll 1
        for (int k = 0; k < cnt; k++) {
            const int s = __shfl_sync(0xffffffffu, sv, k);
            float as = g_asrc[s * HHEADS + head] + ad;
            const uint2 u = *(const uint2*)(g_hh + (size_t)s * DD + 4 * l);
            as = (as > 0.f) ? as : 0.2f * as;
            const float ww = __expf(as);
            wsum += ww;
            const float2 fa = __half22float2(*(const __half2*)&u.x);
            const float2 fb = __half22float2(*(const __half2*)&u.y);
            acc.x += ww * fa.x;
            acc.y += ww * fa.y;
            acc.z += ww * fb.x;
            acc.w += ww * fb.y;
        }
    }

    const float inv = 1.f / (wsum + 1e-16f);
    const float4 xv = ((const float4*)(g_xt + (size_t)n * DD))[l];
    const float4 bv = __ldg(((const float4*)bias) + l);
    float4 v;
    v.x = xv.x + acc.x * inv + bv.x;
    v.y = xv.y + acc.y * inv + bv.y;
    v.z = xv.z + acc.z * inv + bv.z;
    v.w = xv.w + acc.w * inv + bv.w;

    float ssum = v.x + v.y + v.z + v.w;
    float q = v.x * v.x + v.y * v.y + v.z * v.z + v.w * v.w;
#pragma unroll
    for (int o = 16; o >= 1; o >>= 1) {
        ssum += __shfl_xor_sync(0xffffffffu, ssum, o);
        q += __shfl_xor_sync(0xffffffffu, q, o);
    }
    const float m = ssum * (1.f / 128.f);
    const float var = q * (1.f / 128.f) - m * m;
    const float rstd = rsqrtf(var + 1e-5f);
    const float4 gv = __ldg(((const float4*)g2) + l);
    const float4 b2v = __ldg(((const float4*)b2) + l);
    float4 o4;
    o4.x = (v.x - m) * rstd * gv.x + b2v.x;
    o4.y = (v.y - m) * rstd * gv.y + b2v.y;
    o4.z = (v.z - m) * rstd * gv.z + b2v.z;
    o4.w = (v.w - m) * rstd * gv.w + b2v.w;
    ((float4*)(out + (size_t)n * DD))[l] = o4;
}

// ---------------------------------------------------------------------------
extern "C" void kernel_launch(void* const* d_in, const int* in_sizes, int n_in,
                              void* d_out, int out_size) {
    const float* x     = (const float*)d_in[0];
    const int*   ei    = (const int*)d_in[1];
    // d_in[2] edge_attr, d_in[3] timestamps: unused by reference
    const float* Wg    = (const float*)d_in[4];
    const float* att_s = (const float*)d_in[5];
    const float* att_d = (const float*)d_in[6];
    const float* bias  = (const float*)d_in[7];
    const float* g1    = (const float*)d_in[8];
    const float* b1    = (const float*)d_in[9];
    const float* g2    = (const float*)d_in[10];
    const float* b2    = (const float*)d_in[11];
    float* out = (float*)d_out;

    void* p_cnt = nullptr;
    cudaGetSymbolAddress(&p_cnt, g_cnt);

    const int smem_bytes = 4 * 128 * SSTRIDE * (int)sizeof(__nv_bfloat16);  // 139264
    cudaFuncSetAttribute(k_ln_gemm, cudaFuncAttributeMaxDynamicSharedMemorySize, smem_bytes);

    if (g_sh.ok) {
        // Fork: CSR build (branch B) on s2, GEMM path (branch A) on default.
        cudaEventRecord(g_sh.ev_fork, 0);
        cudaStreamWaitEvent(g_sh.s2, g_sh.ev_fork, 0);

        cudaMemsetAsync(p_cnt, 0, (size_t)NN * sizeof(int), g_sh.s2);
        k_hist<<<(EE + 255) / 256, 256, 0, g_sh.s2>>>(ei);
        k_scan_blk<<<SCAN_BLKS, 256, 0, g_sh.s2>>>();
        k_scan_fix<<<SCAN_BLKS, 256, 0, g_sh.s2>>>();
        k_scatter<<<(EE + 255) / 256, 256, 0, g_sh.s2>>>(ei);
        cudaEventRecord(g_sh.ev_join, g_sh.s2);

        k_wconv<<<64, 256>>>(Wg);
        k_ln_gemm<<<(NN + 127) / 128, 512, smem_bytes>>>(x, g1, b1, att_s, att_d);

        // Join, then gather.
        cudaStreamWaitEvent(0, g_sh.ev_join, 0);
        k_gather_out<<<(NN * 32 + 255) / 256, 256>>>(bias, g2, b2, out);
    } else {
        // Fallback: fully serial on default stream (identical to R10).
        cudaMemsetAsync(p_cnt, 0, (size_t)NN * sizeof(int), 0);
        k_wconv<<<64, 256>>>(Wg);
        k_hist<<<(EE + 255) / 256, 256>>>(ei);
        k_ln_gemm<<<(NN + 127) / 128, 512, smem_bytes>>>(x, g1, b1, att_s, att_d);
        k_scan_blk<<<SCAN_BLKS, 256>>>();
        k_scan_fix<<<SCAN_BLKS, 256>>>();
        k_scatter<<<(EE + 255) / 256, 256>>>(ei);
        k_gather_out<<<(NN * 32 + 255) / 256, 256>>>(bias, g2, b2, out);
    }
}

// round 13
// speedup vs baseline: 1.5180x; 1.2834x over previous
#include <cuda_runtime.h>
#include <cuda_bf16.h>
#include <cuda_fp16.h>
#include <cstdint>

#define NN 50000
#define DD 128
#define HHEADS 4
#define CCH 32
#define EE 600000
#define SCAN_BLKS 196  // 196*256 = 50176 >= NN

// Scratch (device globals: no allocation allowed)
__device__ __align__(256) float g_xt[(size_t)NN * DD];
__device__ __align__(256) __half g_hh[(size_t)NN * DD];  // fp16 h
__device__ __align__(256) float g_asrc[NN * HHEADS];
__device__ __align__(256) float g_adst[NN * HHEADS];
__device__ __align__(256) int g_cnt[NN];
__device__ __align__(256) int g_rowstart[NN + 1];
__device__ __align__(256) int g_cursor[NN];
__device__ __align__(256) int g_srcs[EE];
__device__ __align__(256) int g_blocksum[SCAN_BLKS];
// B = W^T as bf16 hi/lo, plain row-major [n][k]
__device__ __align__(256) __nv_bfloat16 g_Bhi[128 * 128];
__device__ __align__(256) __nv_bfloat16 g_Blo[128 * 128];

// ---------------------------------------------------------------------------
// helpers
// ---------------------------------------------------------------------------
__device__ __forceinline__ uint32_t smem_u32(const void* p) {
    uint32_t a;
    asm("{ .reg .u64 t; cvta.to.shared.u64 t, %1; cvt.u32.u64 %0, t; }" : "=r"(a) : "l"(p));
    return a;
}
__device__ __forceinline__ void ldmx4(uint32_t* r, uint32_t addr) {
    asm volatile("ldmatrix.sync.aligned.m8n8.x4.shared.b16 {%0,%1,%2,%3}, [%4];"
                 : "=r"(r[0]), "=r"(r[1]), "=r"(r[2]), "=r"(r[3]) : "r"(addr));
}
__device__ __forceinline__ void ldmx2(uint32_t* r, uint32_t addr) {
    asm volatile("ldmatrix.sync.aligned.m8n8.x2.shared.b16 {%0,%1}, [%2];"
                 : "=r"(r[0]), "=r"(r[1]) : "r"(addr));
}
__device__ __forceinline__ void mma16816(float* d, const uint32_t* a, const uint32_t* b) {
    asm volatile(
        "mma.sync.aligned.m16n8k16.row.col.f32.bf16.bf16.f32 "
        "{%0,%1,%2,%3}, {%4,%5,%6,%7}, {%8,%9}, {%0,%1,%2,%3};"
        : "+f"(d[0]), "+f"(d[1]), "+f"(d[2]), "+f"(d[3])
        : "r"(a[0]), "r"(a[1]), "r"(a[2]), "r"(a[3]), "r"(b[0]), "r"(b[1]));
}

#define SSTRIDE 136  // bf16 elements per smem row (272B: ldmatrix conflict-free)

// ---------------------------------------------------------------------------
// K0: one-time W conversion: Bt[n][k] = W[k][n] -> hi/lo bf16
// ---------------------------------------------------------------------------
__global__ __launch_bounds__(256)
void k_wconv(const float* __restrict__ Wg) {
    const int idx = blockIdx.x * 256 + threadIdx.x;
    if (idx >= 128 * 128) return;
    const int k = idx >> 7;
    const int n = idx & 127;
    const float w = __ldg(Wg + idx);  // W[k][n]
    const __nv_bfloat16 hi = __float2bfloat16(w);
    const __nv_bfloat16 lo = __float2bfloat16(w - __bfloat162float(hi));
    g_Bhi[n * 128 + k] = hi;
    g_Blo[n * 128 + k] = lo;
}

// ---------------------------------------------------------------------------
// K1: fused LayerNorm1 + mma.sync bf16-split GEMM + att-score epilogue.
// 512 threads (16 warps). Tile 128x128, K=128.
// ---------------------------------------------------------------------------
extern __shared__ __nv_bfloat16 smem_bf[];

__global__ __launch_bounds__(512, 1)
void k_ln_gemm(const float* __restrict__ x, const float* __restrict__ g1,
               const float* __restrict__ b1, const float* __restrict__ att_s,
               const float* __restrict__ att_d) {
    __nv_bfloat16* Ahi = smem_bf;
    __nv_bfloat16* Alo = smem_bf + 128 * SSTRIDE;
    __nv_bfloat16* Bhi = smem_bf + 2 * 128 * SSTRIDE;
    __nv_bfloat16* Blo = smem_bf + 3 * 128 * SSTRIDE;

    const int t = threadIdx.x;
    const int lane = t & 31;
    const int wid = t >> 5;
    const int row0 = blockIdx.x * 128;

    // Copy B (hi/lo) into padded smem
    {
        const int row = t >> 2;
        const int col0 = (t & 3) * 32;
        const uint4* sh = (const uint4*)(g_Bhi + row * 128 + col0);
        const uint4* sl = (const uint4*)(g_Blo + row * 128 + col0);
        uint4* dh = (uint4*)(Bhi + row * SSTRIDE + col0);
        uint4* dl = (uint4*)(Blo + row * SSTRIDE + col0);
#pragma unroll
        for (int i = 0; i < 4; i++) { dh[i] = sh[i]; dl[i] = sl[i]; }
    }

    // LayerNorm + A hi/lo into padded smem: 16 warps x 8 rows each
    const float4 gv = __ldg(((const float4*)g1) + lane);
    const float4 bv = __ldg(((const float4*)b1) + lane);
#pragma unroll 1
    for (int i = 0; i < 8; i++) {
        const int r = wid + 16 * i;
        const int gr = row0 + r;
        float4 v = make_float4(0.f, 0.f, 0.f, 0.f);
        if (gr < NN) v = ((const float4*)(x + (size_t)gr * DD))[lane];
        float s = v.x + v.y + v.z + v.w;
        float q = v.x * v.x + v.y * v.y + v.z * v.z + v.w * v.w;
#pragma unroll
        for (int o = 16; o >= 1; o >>= 1) {
            s += __shfl_xor_sync(0xffffffffu, s, o);
            q += __shfl_xor_sync(0xffffffffu, q, o);
        }
        const float m = s * (1.f / 128.f);
        const float var = q * (1.f / 128.f) - m * m;
        const float rstd = rsqrtf(var + 1e-5f);
        float4 o4;
        o4.x = (v.x - m) * rstd * gv.x + bv.x;
        o4.y = (v.y - m) * rstd * gv.y + bv.y;
        o4.z = (v.z - m) * rstd * gv.z + bv.z;
        o4.w = (v.w - m) * rstd * gv.w + bv.w;
        if (gr < NN) ((float4*)(g_xt + (size_t)gr * DD))[lane] = o4;

        __nv_bfloat162 h01 = __floats2bfloat162_rn(o4.x, o4.y);
        __nv_bfloat162 h23 = __floats2bfloat162_rn(o4.z, o4.w);
        __nv_bfloat162 l01 = __floats2bfloat162_rn(o4.x - __bfloat162float(h01.x),
                                                   o4.y - __bfloat162float(h01.y));
        __nv_bfloat162 l23 = __floats2bfloat162_rn(o4.z - __bfloat162float(h23.x),
                                                   o4.w - __bfloat162float(h23.y));
        uint2 hp, lp;
        hp.x = *(const uint32_t*)&h01; hp.y = *(const uint32_t*)&h23;
        lp.x = *(const uint32_t*)&l01; lp.y = *(const uint32_t*)&l23;
        *(uint2*)(Ahi + r * SSTRIDE + 4 * lane) = hp;
        *(uint2*)(Alo + r * SSTRIDE + 4 * lane) = lp;
    }
    __syncthreads();

    // ---- MMA phase: warp -> 32m x 32n ----
    const int mrow = (wid & 3) * 32;
    const int noff = (wid >> 2) * 32;
    const uint32_t sAhi = smem_u32(Ahi);
    const uint32_t sAlo = smem_u32(Alo);
    const uint32_t sBhi = smem_u32(Bhi);
    const uint32_t sBlo = smem_u32(Blo);

    float acc[2][4][4];
#pragma unroll
    for (int mf = 0; mf < 2; mf++)
#pragma unroll
        for (int f = 0; f < 4; f++)
#pragma unroll
            for (int e = 0; e < 4; e++) acc[mf][f][e] = 0.f;

    const int am = lane & 15;
    const int aksel = (lane >> 4) << 3;
    const int bn = lane & 7;
    const int bksel = ((lane >> 3) & 1) << 3;

#pragma unroll 1
    for (int k0 = 0; k0 < 8; k0++) {
        const int ak = k0 * 16 + aksel;
        const int bk = k0 * 16 + bksel;
        uint32_t ah0[4], ah1[4], al0[4], al1[4];
        const uint32_t aoff0 = (uint32_t)(((mrow + am) * SSTRIDE + ak) * 2);
        const uint32_t aoff1 = aoff0 + 16 * SSTRIDE * 2;
        ldmx4(ah0, sAhi + aoff0);
        ldmx4(ah1, sAhi + aoff1);
        ldmx4(al0, sAlo + aoff0);
        ldmx4(al1, sAlo + aoff1);
#pragma unroll
        for (int f = 0; f < 4; f++) {
            const uint32_t boff = (uint32_t)(((noff + 8 * f + bn) * SSTRIDE + bk) * 2);
            uint32_t bh[2], bl[2];
            ldmx2(bh, sBhi + boff);
            ldmx2(bl, sBlo + boff);
            mma16816(acc[0][f], ah0, bh);
            mma16816(acc[1][f], ah1, bh);
            mma16816(acc[0][f], ah0, bl);
            mma16816(acc[1][f], ah1, bl);
            mma16816(acc[0][f], al0, bh);
            mma16816(acc[1][f], al1, bh);
        }
    }

    // ---- Epilogue: store h (fp16) + fused attention scores ----
    const int head = wid >> 2;
    float ps_lo[2] = {0.f, 0.f}, ps_hi[2] = {0.f, 0.f};
    float pd_lo[2] = {0.f, 0.f}, pd_hi[2] = {0.f, 0.f};

#pragma unroll
    for (int f = 0; f < 4; f++) {
        const int c = noff + 8 * f + (lane & 3) * 2;
        const float as0 = __ldg(att_s + c), as1 = __ldg(att_s + c + 1);
        const float ad0 = __ldg(att_d + c), ad1 = __ldg(att_d + c + 1);
#pragma unroll
        for (int mf = 0; mf < 2; mf++) {
            const int r_lo = row0 + mrow + 16 * mf + (lane >> 2);
            const int r_hi = r_lo + 8;
            const float d0 = acc[mf][f][0], d1 = acc[mf][f][1];
            const float d2 = acc[mf][f][2], d3 = acc[mf][f][3];
            if (r_lo < NN) *(__half2*)(g_hh + (size_t)r_lo * DD + c) = __floats2half2_rn(d0, d1);
            if (r_hi < NN) *(__half2*)(g_hh + (size_t)r_hi * DD + c) = __floats2half2_rn(d2, d3);
            ps_lo[mf] += d0 * as0 + d1 * as1;
            ps_hi[mf] += d2 * as0 + d3 * as1;
            pd_lo[mf] += d0 * ad0 + d1 * ad1;
            pd_hi[mf] += d2 * ad0 + d3 * ad1;
        }
    }
#pragma unroll
    for (int mf = 0; mf < 2; mf++) {
#pragma unroll
        for (int o = 1; o <= 2; o <<= 1) {
            ps_lo[mf] += __shfl_xor_sync(0xffffffffu, ps_lo[mf], o);
            ps_hi[mf] += __shfl_xor_sync(0xffffffffu, ps_hi[mf], o);
            pd_lo[mf] += __shfl_xor_sync(0xffffffffu, pd_lo[mf], o);
            pd_hi[mf] += __shfl_xor_sync(0xffffffffu, pd_hi[mf], o);
        }
    }
    if ((lane & 3) == 0) {
#pragma unroll
        for (int mf = 0; mf < 2; mf++) {
            const int r_lo = row0 + mrow + 16 * mf + (lane >> 2);
            const int r_hi = r_lo + 8;
            if (r_lo < NN) {
                g_asrc[r_lo * HHEADS + head] = ps_lo[mf];
                g_adst[r_lo * HHEADS + head] = pd_lo[mf];
            }
            if (r_hi < NN) {
                g_asrc[r_hi * HHEADS + head] = ps_hi[mf];
                g_adst[r_hi * HHEADS + head] = pd_hi[mf];
            }
        }
    }
}

// ---------------------------------------------------------------------------
// K3: degree histogram over dst — int4 vectorized, 4 edges/thread
// ---------------------------------------------------------------------------
__global__ __launch_bounds__(256)
void k_hist(const int* __restrict__ ei) {
    const int q = blockIdx.x * blockDim.x + threadIdx.x;  // quad index
    const int base = q * 4;
    if (base + 3 < EE) {
        const int4 d4 = *(const int4*)(ei + EE + base);
        atomicAdd(&g_cnt[d4.x], 1);
        atomicAdd(&g_cnt[d4.y], 1);
        atomicAdd(&g_cnt[d4.z], 1);
        atomicAdd(&g_cnt[d4.w], 1);
    } else {
        for (int e = base; e < EE; e++) atomicAdd(&g_cnt[__ldg(ei + EE + e)], 1);
    }
}

// ---------------------------------------------------------------------------
// K4a: block-local exclusive scan of g_cnt
// ---------------------------------------------------------------------------
__global__ __launch_bounds__(256)
void k_scan_blk() {
    __shared__ int wsums[8];
    const int t = threadIdx.x;
    const int idx = blockIdx.x * 256 + t;
    const int lane = t & 31, w = t >> 5;
    const int c = (idx < NN) ? g_cnt[idx] : 0;
    int v = c;
#pragma unroll
    for (int o = 1; o < 32; o <<= 1) {
        const int u = __shfl_up_sync(0xffffffffu, v, o);
        if (lane >= o) v += u;
    }
    if (lane == 31) wsums[w] = v;
    __syncthreads();
    if (w == 0) {
        int x2 = (lane < 8) ? wsums[lane] : 0;
#pragma unroll
        for (int o = 1; o < 8; o <<= 1) {
            const int u = __shfl_up_sync(0xffffffffu, x2, o);
            if (lane >= o) x2 += u;
        }
        if (lane < 8) wsums[lane] = x2;
    }
    __syncthreads();
    const int excl = v - c + ((w > 0) ? wsums[w - 1] : 0);
    if (idx < NN) g_rowstart[idx] = excl;
    if (t == 255) g_blocksum[blockIdx.x] = excl + c;
}

// ---------------------------------------------------------------------------
// K4b: add block offsets
// ---------------------------------------------------------------------------
__global__ __launch_bounds__(256)
void k_scan_fix() {
    __shared__ int red[9];
    const int t = threadIdx.x;
    const int blk = blockIdx.x;
    const int lane = t & 31, w = t >> 5;
    int v = (t < blk) ? g_blocksum[t] : 0;
#pragma unroll
    for (int o = 16; o >= 1; o >>= 1) v += __shfl_xor_sync(0xffffffffu, v, o);
    if (lane == 0) red[w] = v;
    __syncthreads();
    if (t == 0) {
        int s = 0;
#pragma unroll
        for (int i = 0; i < 8; i++) s += red[i];
        red[8] = s;
    }
    __syncthreads();
    const int off = red[8];
    const int idx = blk * 256 + t;
    if (idx < NN) {
        const int r = g_rowstart[idx] + off;
        g_rowstart[idx] = r;
        g_cursor[idx] = r;
    }
    if (blk == SCAN_BLKS - 1 && t == 0) g_rowstart[NN] = off + g_blocksum[blk];
}

// ---------------------------------------------------------------------------
// K5: scatter src ids into dst-sorted CSR — int4 vectorized, 4 edges/thread
// ---------------------------------------------------------------------------
__global__ __launch_bounds__(256)
void k_scatter(const int* __restrict__ ei) {
    const int q = blockIdx.x * blockDim.x + threadIdx.x;
    const int base = q * 4;
    if (base + 3 < EE) {
        const int4 s4 = *(const int4*)(ei + base);
        const int4 d4 = *(const int4*)(ei + EE + base);
        const int p0 = atomicAdd(&g_cursor[d4.x], 1);
        const int p1 = atomicAdd(&g_cursor[d4.y], 1);
        const int p2 = atomicAdd(&g_cursor[d4.z], 1);
        const int p3 = atomicAdd(&g_cursor[d4.w], 1);
        g_srcs[p0] = s4.x;
        g_srcs[p1] = s4.y;
        g_srcs[p2] = s4.z;
        g_srcs[p3] = s4.w;
    } else {
        for (int e = base; e < EE; e++) {
            const int s = __ldg(ei + e);
            const int d = __ldg(ei + EE + e);
            const int pos = atomicAdd(&g_cursor[d], 1);
            g_srcs[pos] = s;
        }
    }
}

// ---------------------------------------------------------------------------
// K6: fused gather-aggregate + normalize + residual + LN2. One warp per node.
// (frozen: identical to the 101.2us version)
// ---------------------------------------------------------------------------
__global__ __launch_bounds__(256)
void k_gather_out(const float* __restrict__ bias, const float* __restrict__ g2,
                  const float* __restrict__ b2, float* __restrict__ out) {
    const int g = blockIdx.x * blockDim.x + threadIdx.x;
    const int n = g >> 5;
    if (n >= NN) return;
    const int l = g & 31;
    const int head = l >> 3;

    const float ad = g_adst[n * HHEADS + head];

    // self-loop edge
    float a = g_asrc[n * HHEADS + head] + ad;
    a = (a > 0.f) ? a : 0.2f * a;
    float w = __expf(a);
    float wsum = w;
    float4 acc;
    {
        const uint2 u = *(const uint2*)(g_hh + (size_t)n * DD + 4 * l);
        const float2 fa = __half22float2(*(const __half2*)&u.x);
        const float2 fb = __half22float2(*(const __half2*)&u.y);
        acc = make_float4(w * fa.x, w * fa.y, w * fb.x, w * fb.y);
    }

    const int rs = g_rowstart[n];
    const int re = g_rowstart[n + 1];
#pragma unroll 1
    for (int j = rs; j < re; j += 32) {
        const int cnt = min(32, re - j);
        const int sv = (l < cnt) ? __ldg(g_srcs + j + l) : 0;
#pragma unroll 1
        for (int k = 0; k < cnt; k++) {
            const int s = __shfl_sync(0xffffffffu, sv, k);
            float as = g_asrc[s * HHEADS + head] + ad;
            const uint2 u = *(const uint2*)(g_hh + (size_t)s * DD + 4 * l);
            as = (as > 0.f) ? as : 0.2f * as;
            const float ww = __expf(as);
            wsum += ww;
            const float2 fa = __half22float2(*(const __half2*)&u.x);
            const float2 fb = __half22float2(*(const __half2*)&u.y);
            acc.x += ww * fa.x;
            acc.y += ww * fa.y;
            acc.z += ww * fb.x;
            acc.w += ww * fb.y;
        }
    }

    const float inv = 1.f / (wsum + 1e-16f);
    const float4 xv = ((const float4*)(g_xt + (size_t)n * DD))[l];
    const float4 bv = __ldg(((const float4*)bias) + l);
    float4 v;
    v.x = xv.x + acc.x * inv + bv.x;
    v.y = xv.y + acc.y * inv + bv.y;
    v.z = xv.z + acc.z * inv + bv.z;
    v.w = xv.w + acc.w * inv + bv.w;

    float ssum = v.x + v.y + v.z + v.w;
    float q = v.x * v.x + v.y * v.y + v.z * v.z + v.w * v.w;
#pragma unroll
    for (int o = 16; o >= 1; o >>= 1) {
        ssum += __shfl_xor_sync(0xffffffffu, ssum, o);
        q += __shfl_xor_sync(0xffffffffu, q, o);
    }
    const float m = ssum * (1.f / 128.f);
    const float var = q * (1.f / 128.f) - m * m;
    const float rstd = rsqrtf(var + 1e-5f);
    const float4 gv = __ldg(((const float4*)g2) + l);
    const float4 b2v = __ldg(((const float4*)b2) + l);
    float4 o4;
    o4.x = (v.x - m) * rstd * gv.x + b2v.x;
    o4.y = (v.y - m) * rstd * gv.y + b2v.y;
    o4.z = (v.z - m) * rstd * gv.z + b2v.z;
    o4.w = (v.w - m) * rstd * gv.w + b2v.w;
    ((float4*)(out + (size_t)n * DD))[l] = o4;
}

// ---------------------------------------------------------------------------
extern "C" void kernel_launch(void* const* d_in, const int* in_sizes, int n_in,
                              void* d_out, int out_size) {
    const float* x     = (const float*)d_in[0];
    const int*   ei    = (const int*)d_in[1];
    // d_in[2] edge_attr, d_in[3] timestamps: unused by reference
    const float* Wg    = (const float*)d_in[4];
    const float* att_s = (const float*)d_in[5];
    const float* att_d = (const float*)d_in[6];
    const float* bias  = (const float*)d_in[7];
    const float* g1    = (const float*)d_in[8];
    const float* b1    = (const float*)d_in[9];
    const float* g2    = (const float*)d_in[10];
    const float* b2    = (const float*)d_in[11];
    float* out = (float*)d_out;

    void* p_cnt = nullptr;
    cudaGetSymbolAddress(&p_cnt, g_cnt);
    cudaMemsetAsync(p_cnt, 0, (size_t)NN * sizeof(int), 0);

    const int smem_bytes = 4 * 128 * SSTRIDE * (int)sizeof(__nv_bfloat16);  // 139264
    cudaFuncSetAttribute(k_ln_gemm, cudaFuncAttributeMaxDynamicSharedMemorySize, smem_bytes);

    const int equads = (EE + 3) / 4;
    k_wconv<<<64, 256>>>(Wg);
    k_hist<<<(equads + 255) / 256, 256>>>(ei);
    k_ln_gemm<<<(NN + 127) / 128, 512, smem_bytes>>>(x, g1, b1, att_s, att_d);
    k_scan_blk<<<SCAN_BLKS, 256>>>();
    k_scan_fix<<<SCAN_BLKS, 256>>>();
    k_scatter<<<(equads + 255) / 256, 256>>>(ei);
    k_gather_out<<<(NN * 32 + 255) / 256, 256>>>(bias, g2, b2, out);
}